// round 11
// baseline (speedup 1.0000x reference)
#include <cuda_runtime.h>
#include <cooperative_groups.h>
namespace cg = cooperative_groups;

#define H 4096
#define NIN 17
#define NA 4
#define COLS 32            // columns per cluster (full 128B line)
#define ROWS 1024          // rows per CTA (cluster of 4 covers 4096)
#define T 1024             // 32 warps -> enough MLP to saturate DRAM
#define STRIDE 36          // padded smem row stride in floats

// smem layout (dynamic):
#define OFF_HEBB   0
#define OFF_HIDDEN (ROWS * STRIDE)                 // + ROWS
#define OFF_RED    (OFF_HIDDEN + ROWS)             // + 32*32
#define OFF_CROSS  (OFF_RED + 32 * 32)             // + 4*32
#define OFF_HV     (OFF_CROSS + 4 * 32)            // + 32
#define SMEM_FLOATS (OFF_HV + 32)

__device__ __align__(16) float g_h[H];
__device__ float g_logits[NA + 1];

__global__ void __cluster_dims__(4, 1, 1) __launch_bounds__(T, 1)
fused_cluster(const float* __restrict__ x,
              const float* __restrict__ hidden,
              const float* __restrict__ hebb,
              const float* __restrict__ i2h_w,
              const float* __restrict__ i2h_b,
              const float* __restrict__ w,
              const float* __restrict__ alpha,
              const float* __restrict__ eta,
              float* __restrict__ out)
{
    extern __shared__ float sh[];
    float* sh_hebb   = sh + OFF_HEBB;
    float* sh_hidden = sh + OFF_HIDDEN;
    float* sh_red    = sh + OFF_RED;
    float* sh_cross  = sh + OFF_CROSS;
    float* sh_hv     = sh + OFF_HV;

    cg::cluster_group cluster = cg::this_cluster();
    const unsigned rank = cluster.block_rank();

    const int tid  = threadIdx.x;
    const int q    = tid & 3;          // 8-col chunk within the 32 cols
    const int rloc = tid >> 2;         // 0..255 row lane
    const int warp = tid >> 5;
    const int lane = tid & 31;
    const int jb   = (blockIdx.x >> 2) * COLS;   // cluster column base
    const int i0   = (int)rank * ROWS;           // this CTA's row base
    const float eta_v = __ldg(eta);

    // preamble: this CTA's hidden slice (1024 rows, one load per thread)
    sh_hidden[tid] = hidden[i0 + tid];
    __syncthreads();

    const float4* __restrict__ w4 = (const float4*)w;
    const float4* __restrict__ a4 = (const float4*)alpha;
    const float4* __restrict__ b4 = (const float4*)hebb;

    // ---- Phase 1: stream w/alpha/hebb quadrant; stash hebb in SMEM; partials ----
    float acc[8] = {0.f, 0.f, 0.f, 0.f, 0.f, 0.f, 0.f, 0.f};
    #pragma unroll
    for (int pass = 0; pass < ROWS / 256; ++pass) {     // 4 passes
        const int il = rloc + pass * 256;
        const size_t o4 = ((size_t)(i0 + il) * H + jb + q * 8) >> 2;
        const float4 w0 = __ldg(w4 + o4),     w1 = __ldg(w4 + o4 + 1);
        const float4 a0 = __ldg(a4 + o4),     a1 = __ldg(a4 + o4 + 1);
        const float4 b0 = __ldg(b4 + o4),     b1 = __ldg(b4 + o4 + 1);
        float4* s = (float4*)&sh_hebb[il * STRIDE + q * 8];
        s[0] = b0;
        s[1] = b1;
        const float hv = sh_hidden[il];
        acc[0] = fmaf(hv, fmaf(a0.x, b0.x, w0.x), acc[0]);
        acc[1] = fmaf(hv, fmaf(a0.y, b0.y, w0.y), acc[1]);
        acc[2] = fmaf(hv, fmaf(a0.z, b0.z, w0.z), acc[2]);
        acc[3] = fmaf(hv, fmaf(a0.w, b0.w, w0.w), acc[3]);
        acc[4] = fmaf(hv, fmaf(a1.x, b1.x, w1.x), acc[4]);
        acc[5] = fmaf(hv, fmaf(a1.y, b1.y, w1.y), acc[5]);
        acc[6] = fmaf(hv, fmaf(a1.z, b1.z, w1.z), acc[6]);
        acc[7] = fmaf(hv, fmaf(a1.w, b1.w, w1.w), acc[7]);
    }
    // warp reduce over the 8 row-lanes (xor 4/8/16 keeps q = lane&3)
    #pragma unroll
    for (int o = 4; o <= 16; o <<= 1)
        #pragma unroll
        for (int c = 0; c < 8; ++c)
            acc[c] += __shfl_xor_sync(0xffffffffu, acc[c], o);
    if (lane < 4) {
        #pragma unroll
        for (int c = 0; c < 8; ++c)
            sh_red[warp * 32 + lane * 8 + c] = acc[c];
    }
    __syncthreads();

    // CTA partial per column -> leader's sh_cross via DSMEM
    if (tid < COLS) {
        float s = 0.f;
        #pragma unroll
        for (int wp = 0; wp < 32; ++wp) s += sh_red[wp * 32 + tid];
        float* dst = cluster.map_shared_rank(sh_cross, 0);
        dst[rank * COLS + tid] = s;
    }
    cluster.sync();

    // leader: final reduce + i2h + tanh -> h
    if (rank == 0 && tid < COLS) {
        float s = sh_cross[tid] + sh_cross[COLS + tid]
                + sh_cross[2 * COLS + tid] + sh_cross[3 * COLS + tid];
        const int j = jb + tid;
        float pr = i2h_b[j];
        #pragma unroll
        for (int kk = 0; kk < NIN; ++kk)
            pr = fmaf(x[kk], i2h_w[j * NIN + kk], pr);
        const float hj = tanhf(pr + s);
        g_h[j]     = hj;
        out[5 + j] = hj;
        sh_hv[tid] = hj;
    }
    cluster.sync();

    // broadcast h back to every CTA's smem
    if (tid < COLS) {
        const float* src = cluster.map_shared_rank(sh_hv, 0);
        sh_hv[tid] = src[tid];
    }
    __syncthreads();

    // ---- Phase 3: hebb_new from SMEM stash (no gmem re-read) ----
    const float om = 1.f - eta_v;
    const int  c3  = tid & 31;         // column (warp = 32 consecutive cols = 128B)
    const int  r3  = tid >> 5;         // 0..31 row lane
    const float hj = sh_hv[c3];
    float* __restrict__ outp = out + 5 + H;     // 4B-misaligned -> scalar stores

    #pragma unroll 8
    for (int it = 0; it < ROWS / 32; ++it) {
        const int il = r3 + it * 32;
        const float hb = sh_hebb[il * STRIDE + c3];
        const size_t idx = (size_t)(i0 + il) * H + jb + c3;
        __stcs(outp + idx, fmaf(om, hb, eta_v * sh_hidden[il] * hj));
    }
}

// ---- heads: 5 blocks, one logit each (fixed-order deterministic reduce) ----
__global__ __launch_bounds__(512)
void k_heads(const float* __restrict__ h2o_w,
             const float* __restrict__ h2o_b,
             const float* __restrict__ h2v_w,
             const float* __restrict__ h2v_b)
{
    __shared__ float red[16];
    const int a = blockIdx.x;
    const int tid = threadIdx.x, warp = tid >> 5, lane = tid & 31;
    const float* row = (a < NA) ? (h2o_w + (size_t)a * H) : h2v_w;
    float s = 0.f;
    #pragma unroll
    for (int k = 0; k < H / 512; ++k) {
        const int j = tid + k * 512;
        s = fmaf(g_h[j], row[j], s);
    }
    #pragma unroll
    for (int o = 16; o; o >>= 1) s += __shfl_xor_sync(0xffffffffu, s, o);
    if (lane == 0) red[warp] = s;
    __syncthreads();
    if (tid == 0) {
        float t = (a < NA) ? h2o_b[a] : h2v_b[0];
        #pragma unroll
        for (int wp = 0; wp < 16; ++wp) t += red[wp];
        g_logits[a] = t;
    }
}

// ---- finisher: softmax + value ----
__global__ void k_fin(float* __restrict__ out)
{
    if (threadIdx.x == 0) {
        float lg[NA];
        #pragma unroll
        for (int a = 0; a < NA; ++a) lg[a] = g_logits[a];
        float m = lg[0];
        #pragma unroll
        for (int a = 1; a < NA; ++a) m = fmaxf(m, lg[a]);
        float e[NA], se = 0.f;
        #pragma unroll
        for (int a = 0; a < NA; ++a) { e[a] = expf(lg[a] - m); se += e[a]; }
        const float inv = 1.f / se;
        #pragma unroll
        for (int a = 0; a < NA; ++a) out[a] = e[a] * inv;
        out[NA] = g_logits[NA];
    }
}

extern "C" void kernel_launch(void* const* d_in, const int* in_sizes, int n_in,
                              void* d_out, int out_size)
{
    const float* x      = (const float*)d_in[0];
    const float* hidden = (const float*)d_in[1];
    const float* hebb   = (const float*)d_in[2];
    const float* i2h_w  = (const float*)d_in[3];
    const float* i2h_b  = (const float*)d_in[4];
    const float* w      = (const float*)d_in[5];
    const float* alpha  = (const float*)d_in[6];
    const float* eta    = (const float*)d_in[7];
    const float* h2o_w  = (const float*)d_in[8];
    const float* h2o_b  = (const float*)d_in[9];
    const float* h2v_w  = (const float*)d_in[10];
    const float* h2v_b  = (const float*)d_in[11];
    float* out = (float*)d_out;

    const size_t smem = SMEM_FLOATS * sizeof(float);   // ~156 KB
    cudaFuncSetAttribute(fused_cluster,
                         cudaFuncAttributeMaxDynamicSharedMemorySize, (int)smem);

    fused_cluster<<<(H / COLS) * 4, T, smem>>>(x, hidden, hebb, i2h_w, i2h_b,
                                               w, alpha, eta, out);
    k_heads<<<NA + 1, 512>>>(h2o_w, h2o_b, h2v_w, h2v_b);
    k_fin<<<1, 32>>>(out);
}